// round 2
// baseline (speedup 1.0000x reference)
#include <cuda_runtime.h>
#include <cuda_bf16.h>
#include <cstdint>

#define NN 100000   // nodes per type
#define EE 600000   // edges per relation
#define DD 128      // hidden dim

// Scratch (static device globals — no runtime allocation)
__device__ float g_y[(size_t)NN * DD];   // transformed node features (reused)
__device__ float g_u1[(size_t)NN * DD];  // layer-0 user output

// ---------------------------------------------------------------------------
// 3xTF32 tensor-core GEMM + bias + ReLU:
//   Y[n_rows,128] = relu(X[n_rows,128] @ W[128,128] + b)
// CTA tile 128x128, 256 threads = 8 warps (2 rows x 4 cols), warp tile 64x32.
// X tile and W^T staged in padded shared (stride 132 -> conflict-free frags).
// Each fp32 operand split hi/lo tf32; 3 mma.sync per product => ~1e-6 error.
// ---------------------------------------------------------------------------
__device__ __forceinline__ void split_tf32(float x, uint32_t& hi, uint32_t& lo)
{
    uint32_t h;
    asm("cvt.rna.tf32.f32 %0, %1;" : "=r"(h) : "f"(x));
    float r = x - __uint_as_float(h);
    asm("cvt.rna.tf32.f32 %0, %1;" : "=r"(lo) : "f"(r));
    hi = h;
}

__device__ __forceinline__ void mma_tf32(float c[4], const uint32_t a[4], const uint32_t b[2])
{
    asm volatile(
        "mma.sync.aligned.m16n8k8.row.col.f32.tf32.tf32.f32 "
        "{%0,%1,%2,%3}, {%4,%5,%6,%7}, {%8,%9}, {%0,%1,%2,%3};"
        : "+f"(c[0]), "+f"(c[1]), "+f"(c[2]), "+f"(c[3])
        : "r"(a[0]), "r"(a[1]), "r"(a[2]), "r"(a[3]), "r"(b[0]), "r"(b[1]));
}

#define XS_STRIDE 132   // 128 + 4 pad floats: bank rotation of 4 per row

__global__ __launch_bounds__(256) void gemm_tf32x3(
    const float* __restrict__ X, const float* __restrict__ W,
    const float* __restrict__ bias, float* __restrict__ Y, int n_rows)
{
    extern __shared__ float sm[];
    float* Xs  = sm;                        // [128][132]  X tile (raw fp32)
    float* Wst = sm + 128 * XS_STRIDE;      // [128][132]  W^T (n-major, raw fp32)

    const int tid  = threadIdx.x;
    const int lane = tid & 31;
    const int gid  = lane >> 2;   // group id 0..7
    const int tig  = lane & 3;    // thread-in-group 0..3
    const int wid  = tid >> 5;
    const int wm   = wid & 1;     // warp row 0..1 (64 rows each)
    const int wn   = wid >> 1;    // warp col 0..3 (32 cols each)
    const int row0 = blockIdx.x * 128;

    // ---- Stage X tile: 128 rows x 32 float4 ----
#pragma unroll
    for (int t = 0; t < 16; t++) {
        int idx = tid + t * 256;            // 0..4095
        int r   = idx >> 5;                 // 0..127
        int c   = (idx & 31) << 2;          // 0..124
        float4 v = make_float4(0.f, 0.f, 0.f, 0.f);
        if (row0 + r < n_rows)
            v = *reinterpret_cast<const float4*>(X + (size_t)(row0 + r) * DD + c);
        *reinterpret_cast<float4*>(Xs + r * XS_STRIDE + c) = v;
    }
    // ---- Stage W^T: read W[k][n] float4-coalesced, scatter to Wst[n][k] ----
#pragma unroll
    for (int t = 0; t < 16; t++) {
        int idx = tid + t * 256;            // 0..4095
        int k   = idx >> 5;                 // 0..127
        int n4  = (idx & 31) << 2;          // 0..124
        float4 v = *reinterpret_cast<const float4*>(W + (size_t)k * DD + n4);
        Wst[(n4 + 0) * XS_STRIDE + k] = v.x;
        Wst[(n4 + 1) * XS_STRIDE + k] = v.y;
        Wst[(n4 + 2) * XS_STRIDE + k] = v.z;
        Wst[(n4 + 3) * XS_STRIDE + k] = v.w;
    }
    __syncthreads();

    float c[4][4][4];
#pragma unroll
    for (int i = 0; i < 4; i++)
#pragma unroll
        for (int j = 0; j < 4; j++)
#pragma unroll
            for (int q = 0; q < 4; q++) c[i][j][q] = 0.f;

#pragma unroll
    for (int ks = 0; ks < 16; ks++) {
        const int k0 = ks * 8;

        // A fragments: 4 m-frags of m16k8 (hi/lo)
        uint32_t ah[4][4], al[4][4];
#pragma unroll
        for (int mf = 0; mf < 4; mf++) {
            int rbase = wm * 64 + mf * 16 + gid;
#pragma unroll
            for (int r = 0; r < 4; r++) {
                int row = rbase + (r & 1) * 8;
                int col = k0 + tig + (r >> 1) * 4;
                split_tf32(Xs[row * XS_STRIDE + col], ah[mf][r], al[mf][r]);
            }
        }
        // B fragments: 4 n-frags of k8n8 (hi/lo)
        uint32_t bh[4][2], bl[4][2];
#pragma unroll
        for (int nf = 0; nf < 4; nf++) {
            int n = wn * 32 + nf * 8 + gid;
#pragma unroll
            for (int r = 0; r < 2; r++)
                split_tf32(Wst[n * XS_STRIDE + k0 + tig + r * 4], bh[nf][r], bl[nf][r]);
        }
        // 3xTF32: small cross terms first, hi*hi last
#pragma unroll
        for (int mf = 0; mf < 4; mf++)
#pragma unroll
            for (int nf = 0; nf < 4; nf++) {
                mma_tf32(c[mf][nf], al[mf], bh[nf]);
                mma_tf32(c[mf][nf], ah[mf], bl[nf]);
                mma_tf32(c[mf][nf], ah[mf], bh[nf]);
            }
    }

    // ---- Epilogue: bias + ReLU, float2 stores ----
#pragma unroll
    for (int nf = 0; nf < 4; nf++) {
        int col = wn * 32 + nf * 8 + 2 * tig;
        float2 bb = *reinterpret_cast<const float2*>(bias + col);
#pragma unroll
        for (int mf = 0; mf < 4; mf++) {
            int row = row0 + wm * 64 + mf * 16 + gid;
            if (row < n_rows) {
                float2 o;
                o.x = fmaxf(c[mf][nf][0] + bb.x, 0.f);
                o.y = fmaxf(c[mf][nf][1] + bb.y, 0.f);
                *reinterpret_cast<float2*>(Y + (size_t)row * DD + col) = o;
            }
            if (row + 8 < n_rows) {
                float2 o;
                o.x = fmaxf(c[mf][nf][2] + bb.x, 0.f);
                o.y = fmaxf(c[mf][nf][3] + bb.y, 0.f);
                *reinterpret_cast<float2*>(Y + (size_t)(row + 8) * DD + col) = o;
            }
        }
    }
}

// ---------------------------------------------------------------------------
// Scatter-add: out[dst[e]] += Y[src[e]]  for each edge, one warp per edge.
// 32 lanes x float4 = full 512B row, coalesced gather + vector red atomic.
// ---------------------------------------------------------------------------
__global__ __launch_bounds__(256) void scatter_add_edges(
    const float* __restrict__ Y, const int* __restrict__ src,
    const int* __restrict__ dst, float* __restrict__ out, int n_edges)
{
    int e    = (int)((blockIdx.x * (unsigned)blockDim.x + threadIdx.x) >> 5);
    int lane = threadIdx.x & 31;
    if (e >= n_edges) return;

    int s = __ldg(src + e);
    int d = __ldg(dst + e);

    float4 v = *(reinterpret_cast<const float4*>(Y + (size_t)s * DD) + lane);
    float* o = out + (size_t)d * DD + (lane << 2);
    asm volatile("red.global.add.v4.f32 [%0], {%1,%2,%3,%4};"
                 :: "l"(o), "f"(v.x), "f"(v.y), "f"(v.z), "f"(v.w)
                 : "memory");
}

// ---------------------------------------------------------------------------
extern "C" void kernel_launch(void* const* d_in, const int* in_sizes, int n_in,
                              void* d_out, int out_size)
{
    // Classify inputs by element count (robust to metadata ordering; within-class
    // order matches reference: x_user,x_item | ei_follows,ei_rates | W0f,W0r,W1f,W1r | b...)
    const float* x_user = nullptr;
    const int*   ei_f   = nullptr;
    const int*   ei_r   = nullptr;
    const float* Wm[4]  = {nullptr, nullptr, nullptr, nullptr};
    const float* bm[4]  = {nullptr, nullptr, nullptr, nullptr};
    int xcnt = 0, ecnt = 0, wcnt = 0, bcnt = 0;

    for (int i = 0; i < n_in; i++) {
        int sz = in_sizes[i];
        if (sz == NN * DD) {
            if (xcnt == 0) x_user = (const float*)d_in[i];
            xcnt++;                       // x_item is dead code in the reference
        } else if (sz == 2 * EE) {
            if (ecnt == 0) ei_f = (const int*)d_in[i];
            else           ei_r = (const int*)d_in[i];
            ecnt++;
        } else if (sz == DD * DD) {
            if (wcnt < 4) Wm[wcnt] = (const float*)d_in[i];
            wcnt++;
        } else if (sz == DD) {
            if (bcnt < 4) bm[bcnt] = (const float*)d_in[i];
            bcnt++;
        }
    }

    float* y;  cudaGetSymbolAddress((void**)&y,  g_y);
    float* u1; cudaGetSymbolAddress((void**)&u1, g_u1);

    float* out_xu = (float*)d_out;
    float* out_xi = (float*)d_out + (size_t)NN * DD;

    const int    gemm_blocks = (NN + 127) / 128;
    const size_t gemm_smem   = 2u * 128u * XS_STRIDE * sizeof(float);  // 135168
    cudaFuncSetAttribute(gemm_tf32x3, cudaFuncAttributeMaxDynamicSharedMemorySize,
                         (int)gemm_smem);

    const int scat_blocks = (EE * 32 + 255) / 256;

    // Accumulators must start at zero (d_out is poisoned by the harness)
    cudaMemsetAsync(u1,    0, (size_t)NN * DD * sizeof(float), 0);
    cudaMemsetAsync(d_out, 0, (size_t)out_size * sizeof(float), 0);

    // Layer 0 (only the 'follows' conv is live):
    //   u1 = segsum_follows(relu(x_user @ W0f + b0f))
    gemm_tf32x3<<<gemm_blocks, 256, gemm_smem>>>(x_user, Wm[0], bm[0], y, NN);
    scatter_add_edges<<<scat_blocks, 256>>>(y, ei_f, ei_f + EE, u1, EE);

    // Layer 1 'follows': out_xu = segsum_follows(relu(u1 @ W1f + b1f))
    gemm_tf32x3<<<gemm_blocks, 256, gemm_smem>>>(u1, Wm[2], bm[2], y, NN);
    scatter_add_edges<<<scat_blocks, 256>>>(y, ei_f, ei_f + EE, out_xu, EE);

    // Layer 1 'rates':   out_xi = segsum_rates(relu(u1 @ W1r + b1r))
    gemm_tf32x3<<<gemm_blocks, 256, gemm_smem>>>(u1, Wm[3], bm[3], y, NN);
    scatter_add_edges<<<scat_blocks, 256>>>(y, ei_r, ei_r + EE, out_xi, EE);
}

// round 3
// speedup vs baseline: 1.2229x; 1.2229x over previous
#include <cuda_runtime.h>
#include <cuda_bf16.h>
#include <cstdint>

#define NN 100000   // nodes per type
#define EE 600000   // edges per relation
#define DD 128      // hidden dim

// Scratch (static device globals — no runtime allocation)
__device__ float g_y[(size_t)NN * DD];   // transformed node features (reused)
__device__ float g_u1[(size_t)NN * DD];  // layer-0 user output

// ---------------------------------------------------------------------------
// 3xTF32 tensor-core GEMM + bias + ReLU:
//   Y[n_rows,128] = relu(X[n_rows,128] @ W[128,128] + b)
// CTA tile 128x128, 256 threads = 8 warps (2x4), warp tile 64x32.
// K is processed in chunks of 32. During staging, every element is split ONCE
// into tf32 hi/lo and stored in padded shared planes (stride 36 u32 -> all
// fragment LDS are conflict-free). Inner loop is pure LDS + mma.sync.
// ---------------------------------------------------------------------------
#define PS 36   // padded row stride (u32 elements): bank = 4*gid+tig = lane

__device__ __forceinline__ void split_tf32(float x, uint32_t& hi, uint32_t& lo)
{
    uint32_t h;
    asm("cvt.rna.tf32.f32 %0, %1;" : "=r"(h) : "f"(x));
    float r = x - __uint_as_float(h);
    asm("cvt.rna.tf32.f32 %0, %1;" : "=r"(lo) : "f"(r));
    hi = h;
}

__device__ __forceinline__ void mma_tf32(float c[4], const uint32_t a[4], const uint32_t b[2])
{
    asm volatile(
        "mma.sync.aligned.m16n8k8.row.col.f32.tf32.tf32.f32 "
        "{%0,%1,%2,%3}, {%4,%5,%6,%7}, {%8,%9}, {%0,%1,%2,%3};"
        : "+f"(c[0]), "+f"(c[1]), "+f"(c[2]), "+f"(c[3])
        : "r"(a[0]), "r"(a[1]), "r"(a[2]), "r"(a[3]), "r"(b[0]), "r"(b[1]));
}

__global__ __launch_bounds__(256, 2) void gemm_tf32x3(
    const float* __restrict__ X, const float* __restrict__ W,
    const float* __restrict__ bias, float* __restrict__ Y, int n_rows)
{
    extern __shared__ uint32_t sh[];
    uint32_t* Xh = sh;                   // [128][PS]   X chunk, tf32 hi
    uint32_t* Xl = Xh + 128 * PS;        // [128][PS]   X chunk, tf32 lo
    uint32_t* Wh = Xl + 128 * PS;        // [n=128][PS] W^T chunk, tf32 hi
    uint32_t* Wl = Wh + 128 * PS;        // [n=128][PS] W^T chunk, tf32 lo

    const int tid  = threadIdx.x;
    const int lane = tid & 31;
    const int gid  = lane >> 2;   // 0..7
    const int tig  = lane & 3;    // 0..3
    const int wid  = tid >> 5;
    const int wm   = wid & 1;     // warp row (64 rows)
    const int wn   = wid >> 1;    // warp col (32 cols)
    const int row0 = blockIdx.x * 128;

    float c[4][4][4];
#pragma unroll
    for (int i = 0; i < 4; i++)
#pragma unroll
        for (int j = 0; j < 4; j++)
#pragma unroll
            for (int q = 0; q < 4; q++) c[i][j][q] = 0.f;

    for (int kc = 0; kc < 4; kc++) {
        const int k0 = kc * 32;

        // ---- Stage X chunk [128 rows][32 k], split once per element ----
#pragma unroll
        for (int t = 0; t < 4; t++) {
            int idx = tid + t * 256;          // float4 task 0..1023
            int r   = idx >> 3;               // 0..127
            int c4  = (idx & 7) << 2;         // 0..28
            float4 v = make_float4(0.f, 0.f, 0.f, 0.f);
            if (row0 + r < n_rows)
                v = *reinterpret_cast<const float4*>(X + (size_t)(row0 + r) * DD + k0 + c4);
            uint32_t h, l;
            split_tf32(v.x, h, l); Xh[r * PS + c4 + 0] = h; Xl[r * PS + c4 + 0] = l;
            split_tf32(v.y, h, l); Xh[r * PS + c4 + 1] = h; Xl[r * PS + c4 + 1] = l;
            split_tf32(v.z, h, l); Xh[r * PS + c4 + 2] = h; Xl[r * PS + c4 + 2] = l;
            split_tf32(v.w, h, l); Xh[r * PS + c4 + 3] = h; Xl[r * PS + c4 + 3] = l;
        }
        // ---- Stage W^T chunk [n=128][k=32]: coalesced reads, split once ----
#pragma unroll
        for (int t = 0; t < 4; t++) {
            int idx = tid + t * 256;          // 0..1023
            int n   = idx & 127;              // lanes consecutive -> coalesced
            int k4  = (idx >> 7) << 2;        // 0,4,...,28
#pragma unroll
            for (int j = 0; j < 4; j++) {
                float w = W[(size_t)(k0 + k4 + j) * DD + n];
                uint32_t h, l;
                split_tf32(w, h, l);
                Wh[n * PS + k4 + j] = h;
                Wl[n * PS + k4 + j] = l;
            }
        }
        __syncthreads();

        // ---- Compute: 4 k-steps of 8 ----
#pragma unroll
        for (int ks = 0; ks < 4; ks++) {
            const int kk = ks * 8;

            uint32_t ah[4][4], al[4][4];
#pragma unroll
            for (int mf = 0; mf < 4; mf++) {
                int rbase = wm * 64 + mf * 16 + gid;
#pragma unroll
                for (int r = 0; r < 4; r++) {
                    int row = rbase + (r & 1) * 8;
                    int col = kk + tig + (r >> 1) * 4;
                    ah[mf][r] = Xh[row * PS + col];
                    al[mf][r] = Xl[row * PS + col];
                }
            }
#pragma unroll
            for (int nf = 0; nf < 4; nf++) {
                int n = wn * 32 + nf * 8 + gid;
                uint32_t bh[2], bl[2];
#pragma unroll
                for (int r = 0; r < 2; r++) {
                    bh[r] = Wh[n * PS + kk + tig + r * 4];
                    bl[r] = Wl[n * PS + kk + tig + r * 4];
                }
#pragma unroll
                for (int mf = 0; mf < 4; mf++) {
                    mma_tf32(c[mf][nf], al[mf], bh);
                    mma_tf32(c[mf][nf], ah[mf], bl);
                    mma_tf32(c[mf][nf], ah[mf], bh);
                }
            }
        }
        __syncthreads();
    }

    // ---- Epilogue: bias + ReLU, float2 stores ----
#pragma unroll
    for (int nf = 0; nf < 4; nf++) {
        int col = wn * 32 + nf * 8 + 2 * tig;
        float2 bb = *reinterpret_cast<const float2*>(bias + col);
#pragma unroll
        for (int mf = 0; mf < 4; mf++) {
            int row = row0 + wm * 64 + mf * 16 + gid;
            if (row < n_rows) {
                float2 o;
                o.x = fmaxf(c[mf][nf][0] + bb.x, 0.f);
                o.y = fmaxf(c[mf][nf][1] + bb.y, 0.f);
                *reinterpret_cast<float2*>(Y + (size_t)row * DD + col) = o;
            }
            if (row + 8 < n_rows) {
                float2 o;
                o.x = fmaxf(c[mf][nf][2] + bb.x, 0.f);
                o.y = fmaxf(c[mf][nf][3] + bb.y, 0.f);
                *reinterpret_cast<float2*>(Y + (size_t)(row + 8) * DD + col) = o;
            }
        }
    }
}

// ---------------------------------------------------------------------------
// Scatter-add: out[dst[e]] += Y[src[e]]  for each edge, one warp per edge.
// 32 lanes x float4 = full 512B row, coalesced gather + vector red atomic.
// ---------------------------------------------------------------------------
__global__ __launch_bounds__(256) void scatter_add_edges(
    const float* __restrict__ Y, const int* __restrict__ src,
    const int* __restrict__ dst, float* __restrict__ out, int n_edges)
{
    int e    = (int)((blockIdx.x * (unsigned)blockDim.x + threadIdx.x) >> 5);
    int lane = threadIdx.x & 31;
    if (e >= n_edges) return;

    int s = __ldg(src + e);
    int d = __ldg(dst + e);

    float4 v = *(reinterpret_cast<const float4*>(Y + (size_t)s * DD) + lane);
    float* o = out + (size_t)d * DD + (lane << 2);
    asm volatile("red.global.add.v4.f32 [%0], {%1,%2,%3,%4};"
                 :: "l"(o), "f"(v.x), "f"(v.y), "f"(v.z), "f"(v.w)
                 : "memory");
}

// ---------------------------------------------------------------------------
extern "C" void kernel_launch(void* const* d_in, const int* in_sizes, int n_in,
                              void* d_out, int out_size)
{
    // Classify inputs by element count (robust to metadata ordering; within-class
    // order matches reference: x_user,x_item | ei_follows,ei_rates | W0f,W0r,W1f,W1r | b...)
    const float* x_user = nullptr;
    const int*   ei_f   = nullptr;
    const int*   ei_r   = nullptr;
    const float* Wm[4]  = {nullptr, nullptr, nullptr, nullptr};
    const float* bm[4]  = {nullptr, nullptr, nullptr, nullptr};
    int xcnt = 0, ecnt = 0, wcnt = 0, bcnt = 0;

    for (int i = 0; i < n_in; i++) {
        int sz = in_sizes[i];
        if (sz == NN * DD) {
            if (xcnt == 0) x_user = (const float*)d_in[i];
            xcnt++;                       // x_item is dead code in the reference
        } else if (sz == 2 * EE) {
            if (ecnt == 0) ei_f = (const int*)d_in[i];
            else           ei_r = (const int*)d_in[i];
            ecnt++;
        } else if (sz == DD * DD) {
            if (wcnt < 4) Wm[wcnt] = (const float*)d_in[i];
            wcnt++;
        } else if (sz == DD) {
            if (bcnt < 4) bm[bcnt] = (const float*)d_in[i];
            bcnt++;
        }
    }

    float* y;  cudaGetSymbolAddress((void**)&y,  g_y);
    float* u1; cudaGetSymbolAddress((void**)&u1, g_u1);

    float* out_xu = (float*)d_out;
    float* out_xi = (float*)d_out + (size_t)NN * DD;

    const int    gemm_blocks = (NN + 127) / 128;
    const size_t gemm_smem   = 4u * 128u * PS * sizeof(uint32_t);  // 73728 B
    cudaFuncSetAttribute(gemm_tf32x3, cudaFuncAttributeMaxDynamicSharedMemorySize,
                         (int)gemm_smem);

    const int scat_blocks = (EE * 32 + 255) / 256;

    // Accumulators must start at zero (d_out is poisoned by the harness)
    cudaMemsetAsync(u1,    0, (size_t)NN * DD * sizeof(float), 0);
    cudaMemsetAsync(d_out, 0, (size_t)out_size * sizeof(float), 0);

    // Layer 0 (only the 'follows' conv is live):
    //   u1 = segsum_follows(relu(x_user @ W0f + b0f))
    gemm_tf32x3<<<gemm_blocks, 256, gemm_smem>>>(x_user, Wm[0], bm[0], y, NN);
    scatter_add_edges<<<scat_blocks, 256>>>(y, ei_f, ei_f + EE, u1, EE);

    // Layer 1 'follows': out_xu = segsum_follows(relu(u1 @ W1f + b1f))
    gemm_tf32x3<<<gemm_blocks, 256, gemm_smem>>>(u1, Wm[2], bm[2], y, NN);
    scatter_add_edges<<<scat_blocks, 256>>>(y, ei_f, ei_f + EE, out_xu, EE);

    // Layer 1 'rates':   out_xi = segsum_rates(relu(u1 @ W1r + b1r))
    gemm_tf32x3<<<gemm_blocks, 256, gemm_smem>>>(u1, Wm[3], bm[3], y, NN);
    scatter_add_edges<<<scat_blocks, 256>>>(y, ei_r, ei_r + EE, out_xi, EE);
}

// round 4
// speedup vs baseline: 1.6258x; 1.3294x over previous
#include <cuda_runtime.h>
#include <cuda_bf16.h>
#include <cstdint>

#define NN 100000   // nodes per type
#define EE 600000   // edges per relation
#define DD 128      // hidden dim
#define NB 98       // scan blocks: ceil(NN/1024)

// ---------------- scratch (static device globals) ----------------
__device__ float g_y[(size_t)NN * DD];    // transformed node features (reused)
__device__ float g_u1[(size_t)NN * DD];   // layer-0 user output
__device__ int   g_cnt[2][NN];            // per-relation histogram / cursor
__device__ int   g_rowptr[2][NN + 1];     // CSC row pointers (by dst)
__device__ int   g_perm[2][EE];           // src ids sorted by dst
__device__ int   g_part[2][NB];           // scan partials

// ===================== CSR (CSC-by-dst) build =====================
__global__ void hist_kernel(const int* __restrict__ dst, int* __restrict__ cnt, int ne)
{
    int e = blockIdx.x * blockDim.x + threadIdx.x;
    if (e < ne) atomicAdd(&cnt[dst[e]], 1);
}

__global__ __launch_bounds__(1024) void block_reduce(
    const int* __restrict__ cnt, int* __restrict__ part, int n)
{
    __shared__ int s[1024];
    int t = threadIdx.x;
    int idx = blockIdx.x * 1024 + t;
    s[t] = (idx < n) ? cnt[idx] : 0;
    __syncthreads();
#pragma unroll
    for (int off = 512; off > 0; off >>= 1) {
        if (t < off) s[t] += s[t + off];
        __syncthreads();
    }
    if (t == 0) part[blockIdx.x] = s[0];
}

__global__ __launch_bounds__(128) void scan_partials(int* __restrict__ part, int nb)
{
    __shared__ int s[128];
    int t = threadIdx.x;
    int v = (t < nb) ? part[t] : 0;
    s[t] = v;
    __syncthreads();
#pragma unroll
    for (int off = 1; off < 128; off <<= 1) {
        int x = (t >= off) ? s[t - off] : 0;
        __syncthreads();
        s[t] += x;
        __syncthreads();
    }
    if (t < nb) part[t] = s[t] - v;   // exclusive
}

__global__ __launch_bounds__(1024) void block_scan_write(
    const int* __restrict__ cnt, const int* __restrict__ part,
    int* __restrict__ rowptr, int* __restrict__ cursor, int n, int total)
{
    __shared__ int s[1024];
    int t = threadIdx.x;
    int idx = blockIdx.x * 1024 + t;
    int v = (idx < n) ? cnt[idx] : 0;
    s[t] = v;
    __syncthreads();
#pragma unroll
    for (int off = 1; off < 1024; off <<= 1) {
        int x = (t >= off) ? s[t - off] : 0;
        __syncthreads();
        s[t] += x;
        __syncthreads();
    }
    int excl = s[t] - v + part[blockIdx.x];
    if (idx < n) { rowptr[idx] = excl; cursor[idx] = excl; }
    if (idx == 0) rowptr[n] = total;
}

__global__ void fill_kernel(const int* __restrict__ src, const int* __restrict__ dst,
                            int* __restrict__ cursor, int* __restrict__ perm, int ne)
{
    int e = blockIdx.x * blockDim.x + threadIdx.x;
    if (e < ne) {
        int p = atomicAdd(&cursor[dst[e]], 1);
        perm[p] = src[e];
    }
}

// ===================== gather (atomic-free segment sum) =====================
// One warp per dst node: out[d] = sum_{j in [rowptr[d],rowptr[d+1])} Y[perm[j]]
__global__ __launch_bounds__(256) void gather_rows(
    const float* __restrict__ Y, const int* __restrict__ rowptr,
    const int* __restrict__ perm, float* __restrict__ out, int n)
{
    int w    = (int)((blockIdx.x * (unsigned)blockDim.x + threadIdx.x) >> 5);
    int lane = threadIdx.x & 31;
    if (w >= n) return;

    int beg = __ldg(rowptr + w);
    int end = __ldg(rowptr + w + 1);

    const float4* Yv = reinterpret_cast<const float4*>(Y);
    float4 acc = make_float4(0.f, 0.f, 0.f, 0.f);

    for (int j0 = beg; j0 < end; j0 += 32) {
        int j  = j0 + lane;
        int sl = (j < end) ? __ldg(perm + j) : 0;
        int m  = min(32, end - j0);
        for (int t = 0; t < m; t++) {
            int s = __shfl_sync(0xffffffffu, sl, t);
            float4 v = Yv[(size_t)s * 32 + lane];
            acc.x += v.x; acc.y += v.y; acc.z += v.z; acc.w += v.w;
        }
    }
    reinterpret_cast<float4*>(out)[(size_t)w * 32 + lane] = acc;
}

// ===================== 3xBF16 tensor-core GEMM =====================
//   Y[n_rows,128] = relu(X[n_rows,128] @ W[128,128] + b)
// CTA 128x128, 8 warps (2x4), warp tile 64x32, mma.m16n8k16.bf16.
// fp32 operands split once into bf16 hi/lo during staging, stored as packed
// bf16x2 u32 planes with stride 36 (bank = 4*gid+tig = lane, conflict-free).
#define PS2 36

__device__ __forceinline__ uint32_t pack2(__nv_bfloat16 lo, __nv_bfloat16 hi)
{
    return (uint32_t)__bfloat16_as_ushort(lo) | ((uint32_t)__bfloat16_as_ushort(hi) << 16);
}

__device__ __forceinline__ void split2(float x, float y, uint32_t& h, uint32_t& l)
{
    __nv_bfloat16 hx = __float2bfloat16_rn(x);
    __nv_bfloat16 hy = __float2bfloat16_rn(y);
    __nv_bfloat16 lx = __float2bfloat16_rn(x - __bfloat162float(hx));
    __nv_bfloat16 ly = __float2bfloat16_rn(y - __bfloat162float(hy));
    h = pack2(hx, hy);
    l = pack2(lx, ly);
}

__device__ __forceinline__ void mma_bf16(float c[4], const uint32_t a[4], const uint32_t b[2])
{
    asm volatile(
        "mma.sync.aligned.m16n8k16.row.col.f32.bf16.bf16.f32 "
        "{%0,%1,%2,%3}, {%4,%5,%6,%7}, {%8,%9}, {%0,%1,%2,%3};"
        : "+f"(c[0]), "+f"(c[1]), "+f"(c[2]), "+f"(c[3])
        : "r"(a[0]), "r"(a[1]), "r"(a[2]), "r"(a[3]), "r"(b[0]), "r"(b[1]));
}

__global__ __launch_bounds__(256, 2) void gemm_bf16x3(
    const float* __restrict__ X, const float* __restrict__ W,
    const float* __restrict__ bias, float* __restrict__ Y, int n_rows)
{
    extern __shared__ uint32_t sh[];
    uint32_t* Xh = sh;                 // [128][PS2]  X chunk hi (bf16x2)
    uint32_t* Xl = Xh + 128 * PS2;     // [128][PS2]  X chunk lo
    uint32_t* Wh = Xl + 128 * PS2;     // [n=128][PS2] W^T chunk hi
    uint32_t* Wl = Wh + 128 * PS2;     // [n=128][PS2] W^T chunk lo

    const int tid  = threadIdx.x;
    const int lane = tid & 31;
    const int gid  = lane >> 2;
    const int tig  = lane & 3;
    const int wid  = tid >> 5;
    const int wm   = wid & 1;
    const int wn   = wid >> 1;
    const int row0 = blockIdx.x * 128;

    float c[4][4][4];
#pragma unroll
    for (int i = 0; i < 4; i++)
#pragma unroll
        for (int j = 0; j < 4; j++)
#pragma unroll
            for (int q = 0; q < 4; q++) c[i][j][q] = 0.f;

#pragma unroll
    for (int kc = 0; kc < 2; kc++) {
        const int k0 = kc * 64;
        if (kc) __syncthreads();   // previous chunk fully consumed

        // ---- stage X chunk: 128 rows x 16 float4, split once ----
#pragma unroll
        for (int t = 0; t < 8; t++) {
            int idx = tid + t * 256;           // 0..2047
            int r   = idx >> 4;                // 0..127
            int c4  = (idx & 15) << 2;         // 0..60 (float offset in chunk)
            float4 v = make_float4(0.f, 0.f, 0.f, 0.f);
            if (row0 + r < n_rows)
                v = *reinterpret_cast<const float4*>(X + (size_t)(row0 + r) * DD + k0 + c4);
            int kp = c4 >> 1;                  // pair index, even
            uint32_t h, l;
            split2(v.x, v.y, h, l); Xh[r * PS2 + kp]     = h; Xl[r * PS2 + kp]     = l;
            split2(v.z, v.w, h, l); Xh[r * PS2 + kp + 1] = h; Xl[r * PS2 + kp + 1] = l;
        }
        // ---- stage W^T chunk: task (n, kp), coalesced over n ----
#pragma unroll
        for (int t = 0; t < 16; t++) {
            int idx = tid + t * 256;           // 0..4095
            int n   = idx & 127;
            int kp  = idx >> 7;                // 0..31
            int k   = k0 + 2 * kp;
            float w0 = W[(size_t)k * DD + n];
            float w1 = W[(size_t)(k + 1) * DD + n];
            uint32_t h, l;
            split2(w0, w1, h, l);
            Wh[n * PS2 + kp] = h;
            Wl[n * PS2 + kp] = l;
        }
        __syncthreads();

        // ---- compute: 4 k16-steps per chunk ----
#pragma unroll
        for (int ks = 0; ks < 4; ks++) {
            const int kb = ks * 8;             // kp base of this k16 step

            uint32_t bh[4][2], bl[4][2];
#pragma unroll
            for (int nf = 0; nf < 4; nf++) {
                int n = wn * 32 + nf * 8 + gid;
                bh[nf][0] = Wh[n * PS2 + kb + tig];
                bh[nf][1] = Wh[n * PS2 + kb + tig + 4];
                bl[nf][0] = Wl[n * PS2 + kb + tig];
                bl[nf][1] = Wl[n * PS2 + kb + tig + 4];
            }
#pragma unroll
            for (int mf = 0; mf < 4; mf++) {
                int r0 = wm * 64 + mf * 16 + gid;
                uint32_t ah[4], al[4];
                ah[0] = Xh[r0 * PS2 + kb + tig];
                ah[1] = Xh[(r0 + 8) * PS2 + kb + tig];
                ah[2] = Xh[r0 * PS2 + kb + tig + 4];
                ah[3] = Xh[(r0 + 8) * PS2 + kb + tig + 4];
                al[0] = Xl[r0 * PS2 + kb + tig];
                al[1] = Xl[(r0 + 8) * PS2 + kb + tig];
                al[2] = Xl[r0 * PS2 + kb + tig + 4];
                al[3] = Xl[(r0 + 8) * PS2 + kb + tig + 4];
#pragma unroll
                for (int nf = 0; nf < 4; nf++) {
                    mma_bf16(c[mf][nf], al, bh[nf]);
                    mma_bf16(c[mf][nf], ah, bl[nf]);
                    mma_bf16(c[mf][nf], ah, bh[nf]);
                }
            }
        }
    }

    // ---- epilogue: bias + ReLU, float2 stores ----
#pragma unroll
    for (int nf = 0; nf < 4; nf++) {
        int col = wn * 32 + nf * 8 + 2 * tig;
        float2 bb = *reinterpret_cast<const float2*>(bias + col);
#pragma unroll
        for (int mf = 0; mf < 4; mf++) {
            int row = row0 + wm * 64 + mf * 16 + gid;
            if (row < n_rows) {
                float2 o;
                o.x = fmaxf(c[mf][nf][0] + bb.x, 0.f);
                o.y = fmaxf(c[mf][nf][1] + bb.y, 0.f);
                *reinterpret_cast<float2*>(Y + (size_t)row * DD + col) = o;
            }
            if (row + 8 < n_rows) {
                float2 o;
                o.x = fmaxf(c[mf][nf][2] + bb.x, 0.f);
                o.y = fmaxf(c[mf][nf][3] + bb.y, 0.f);
                *reinterpret_cast<float2*>(Y + (size_t)(row + 8) * DD + col) = o;
            }
        }
    }
}

// ===================== launch =====================
extern "C" void kernel_launch(void* const* d_in, const int* in_sizes, int n_in,
                              void* d_out, int out_size)
{
    const float* x_user = nullptr;
    const int*   ei_f   = nullptr;
    const int*   ei_r   = nullptr;
    const float* Wm[4]  = {nullptr, nullptr, nullptr, nullptr};
    const float* bm[4]  = {nullptr, nullptr, nullptr, nullptr};
    int xcnt = 0, ecnt = 0, wcnt = 0, bcnt = 0;

    for (int i = 0; i < n_in; i++) {
        int sz = in_sizes[i];
        if (sz == NN * DD) {
            if (xcnt == 0) x_user = (const float*)d_in[i];
            xcnt++;                        // x_item is dead code in the reference
        } else if (sz == 2 * EE) {
            if (ecnt == 0) ei_f = (const int*)d_in[i];
            else           ei_r = (const int*)d_in[i];
            ecnt++;
        } else if (sz == DD * DD) {
            if (wcnt < 4) Wm[wcnt] = (const float*)d_in[i];
            wcnt++;
        } else if (sz == DD) {
            if (bcnt < 4) bm[bcnt] = (const float*)d_in[i];
            bcnt++;
        }
    }

    float* y;   cudaGetSymbolAddress((void**)&y,   g_y);
    float* u1;  cudaGetSymbolAddress((void**)&u1,  g_u1);
    int*   cnt; cudaGetSymbolAddress((void**)&cnt, g_cnt);
    int*   rp;  cudaGetSymbolAddress((void**)&rp,  g_rowptr);
    int*   pm;  cudaGetSymbolAddress((void**)&pm,  g_perm);
    int*   pt;  cudaGetSymbolAddress((void**)&pt,  g_part);

    int* cnt_r  = cnt + NN;
    int* rp_r   = rp + (NN + 1);
    int* pm_r   = pm + EE;
    int* pt_r   = pt + NB;

    float* out_xu = (float*)d_out;
    float* out_xi = (float*)d_out + (size_t)NN * DD;

    const int* src_f = ei_f;
    const int* dst_f = ei_f + EE;
    const int* src_r = ei_r;
    const int* dst_r = ei_r + EE;

    const int eb = (EE + 255) / 256;
    const int gb = (NN * 32 + 255) / 256;

    // ---- build CSC for both relations ----
    cudaMemsetAsync(cnt, 0, 2u * NN * sizeof(int), 0);
    hist_kernel<<<eb, 256>>>(dst_f, cnt,   EE);
    hist_kernel<<<eb, 256>>>(dst_r, cnt_r, EE);
    block_reduce<<<NB, 1024>>>(cnt,   pt,   NN);
    block_reduce<<<NB, 1024>>>(cnt_r, pt_r, NN);
    scan_partials<<<1, 128>>>(pt,   NB);
    scan_partials<<<1, 128>>>(pt_r, NB);
    block_scan_write<<<NB, 1024>>>(cnt,   pt,   rp,   cnt,   NN, EE);  // cursor reuses cnt
    block_scan_write<<<NB, 1024>>>(cnt_r, pt_r, rp_r, cnt_r, NN, EE);
    fill_kernel<<<eb, 256>>>(src_f, dst_f, cnt,   pm,   EE);
    fill_kernel<<<eb, 256>>>(src_r, dst_r, cnt_r, pm_r, EE);

    // ---- GEMM setup ----
    const int    gemm_blocks = (NN + 127) / 128;
    const size_t gemm_smem   = 4u * 128u * PS2 * sizeof(uint32_t);  // 73728 B
    cudaFuncSetAttribute(gemm_bf16x3, cudaFuncAttributeMaxDynamicSharedMemorySize,
                         (int)gemm_smem);

    // Layer 0 ('follows' only is live): u1 = segsum_f(relu(x_user @ W0f + b0f))
    gemm_bf16x3<<<gemm_blocks, 256, gemm_smem>>>(x_user, Wm[0], bm[0], y, NN);
    gather_rows<<<gb, 256>>>(y, rp, pm, u1, NN);

    // Layer 1 'follows': out_xu = segsum_f(relu(u1 @ W1f + b1f))
    gemm_bf16x3<<<gemm_blocks, 256, gemm_smem>>>(u1, Wm[2], bm[2], y, NN);
    gather_rows<<<gb, 256>>>(y, rp, pm, out_xu, NN);

    // Layer 1 'rates': out_xi = segsum_r(relu(u1 @ W1r + b1r))
    gemm_bf16x3<<<gemm_blocks, 256, gemm_smem>>>(u1, Wm[3], bm[3], y, NN);
    gather_rows<<<gb, 256>>>(y, rp_r, pm_r, out_xi, NN);
}